// round 1
// baseline (speedup 1.0000x reference)
#include <cuda_runtime.h>
#include <math.h>

#define D_MODEL 1024
#define N_HEADS 16
#define HEAD_DIM 64
#define BATCH 4
#define SEQ 2048
#define M_ROWS (BATCH * SEQ)   // 8192

// Scratch (allocation-free rule: __device__ globals)
__device__ float g_q[M_ROWS * D_MODEL];
__device__ float g_k[M_ROWS * D_MODEL];
__device__ float g_v[M_ROWS * D_MODEL];
__device__ float g_att[M_ROWS * D_MODEL];

// ---------------------------------------------------------------------------
// SGEMM: C[M,N] = A[M,K] @ W[N,K]^T   (A row-major, W row-major with K contig)
// Tile: 128x64, K-step 16, 256 threads, 8x4 micro-tile per thread.
// ---------------------------------------------------------------------------
__global__ __launch_bounds__(256) void gemm_nt_kernel(
    const float* __restrict__ A, const float* __restrict__ W,
    float* __restrict__ C, int M, int N, int K)
{
    __shared__ float As[16][132];   // [kk][m], padded (132 % 32 == 4): float4-aligned rows
    __shared__ float Bs[16][68];    // [kk][n]

    const int tid = threadIdx.x;
    const int tx = tid & 15;        // 0..15 -> col group
    const int ty = tid >> 4;        // 0..15 -> row group
    const int row0 = blockIdx.y * 128;
    const int col0 = blockIdx.x * 64;

    float c[8][4];
#pragma unroll
    for (int i = 0; i < 8; i++)
#pragma unroll
        for (int j = 0; j < 4; j++) c[i][j] = 0.0f;

    for (int k0 = 0; k0 < K; k0 += 16) {
        // Load A tile 128x16 (transposed into As[kk][m])
#pragma unroll
        for (int it = 0; it < 8; it++) {
            int i = tid + it * 256;
            int m  = i >> 4;
            int kk = i & 15;
            As[kk][m] = A[(size_t)(row0 + m) * K + (k0 + kk)];
        }
        // Load W tile 64x16
#pragma unroll
        for (int it = 0; it < 4; it++) {
            int i = tid + it * 256;
            int n  = i >> 4;
            int kk = i & 15;
            Bs[kk][n] = W[(size_t)(col0 + n) * K + (k0 + kk)];
        }
        __syncthreads();

#pragma unroll
        for (int kk = 0; kk < 16; kk++) {
            float4 a0 = *(const float4*)&As[kk][ty * 8];
            float4 a1 = *(const float4*)&As[kk][ty * 8 + 4];
            float4 bv = *(const float4*)&Bs[kk][tx * 4];
            float a[8] = {a0.x, a0.y, a0.z, a0.w, a1.x, a1.y, a1.z, a1.w};
            float b[4] = {bv.x, bv.y, bv.z, bv.w};
#pragma unroll
            for (int i = 0; i < 8; i++)
#pragma unroll
                for (int j = 0; j < 4; j++)
                    c[i][j] = fmaf(a[i], b[j], c[i][j]);
        }
        __syncthreads();
    }

#pragma unroll
    for (int i = 0; i < 8; i++) {
        int rm = row0 + ty * 8 + i;
        float4 v = make_float4(c[i][0], c[i][1], c[i][2], c[i][3]);
        *(float4*)&C[(size_t)rm * N + col0 + tx * 4] = v;
    }
}

// ---------------------------------------------------------------------------
// RoPE (in-place on g_q, g_k). One thread per (bt, h, d<32) pair.
// Double-precision sincos: ang up to ~2047 rad, avoid fast-math sin error.
// ---------------------------------------------------------------------------
__global__ void rope_kernel()
{
    int idx = blockIdx.x * blockDim.x + threadIdx.x;
    const int total = M_ROWS * N_HEADS * 32;
    if (idx >= total) return;

    int d  = idx & 31;
    int h  = (idx >> 5) & (N_HEADS - 1);
    int bt = idx >> 9;              // /(16*32)
    int t  = bt & (SEQ - 1);

    double inv = pow(10000.0, -(double)d / 32.0);
    double ang = (double)t * inv;
    double sn, cs;
    sincos(ang, &sn, &cs);
    float s = (float)sn, c = (float)cs;

    size_t base = (size_t)bt * D_MODEL + h * HEAD_DIM + d;
    float x1 = g_q[base], x2 = g_q[base + 32];
    g_q[base]      = x1 * c - x2 * s;
    g_q[base + 32] = x2 * c + x1 * s;
    x1 = g_k[base]; x2 = g_k[base + 32];
    g_k[base]      = x1 * c - x2 * s;
    g_k[base + 32] = x2 * c + x1 * s;
}

// ---------------------------------------------------------------------------
// Causal flash attention. Block: 128 query rows, 128 threads (1 row/thread).
// K/V streamed in 32-key tiles via smem (broadcast reads). Online softmax.
// Output written in [B, T, H*Dh] layout (ready for O-projection GEMM).
// ---------------------------------------------------------------------------
__global__ __launch_bounds__(128) void flash_kernel()
{
    __shared__ float Ks[32][64];
    __shared__ float Vs[32][64];
    __shared__ float Ss[128][33];   // per-thread score staging, pad -> conflict-free

    const int r  = threadIdx.x;
    const int q0 = blockIdx.x * 128;
    const int h  = blockIdx.y;
    const int b  = blockIdx.z;
    const int qi = q0 + r;
    const int hoff = h * HEAD_DIM;

    const float* qptr  = g_q + (size_t)(b * SEQ + qi) * D_MODEL + hoff;
    const float* kbase = g_k + (size_t)(b * SEQ) * D_MODEL + hoff;
    const float* vbase = g_v + (size_t)(b * SEQ) * D_MODEL + hoff;

    float q[64];
#pragma unroll
    for (int j = 0; j < 64; j += 4) {
        float4 t4 = *(const float4*)(qptr + j);
        q[j] = t4.x; q[j + 1] = t4.y; q[j + 2] = t4.z; q[j + 3] = t4.w;
    }

    float o[64];
#pragma unroll
    for (int j = 0; j < 64; j++) o[j] = 0.0f;
    float mrun = -1e30f, l = 0.0f;

    const int ntiles = q0 / 32 + 4;   // covers keys up to q0+127
    const float scale = 0.125f;       // 1/sqrt(64)

    for (int kt = 0; kt < ntiles; kt++) {
        const int kstart = kt * 32;
        // Cooperative K/V tile load: 32 rows x 16 float4 each
#pragma unroll
        for (int it = 0; it < 4; it++) {
            int i = r + it * 128;
            int rowk = i >> 4;
            int c4 = (i & 15) * 4;
            size_t goff = (size_t)(kstart + rowk) * D_MODEL + c4;
            *(float4*)&Ks[rowk][c4] = *(const float4*)(kbase + goff);
            *(float4*)&Vs[rowk][c4] = *(const float4*)(vbase + goff);
        }
        __syncthreads();

        if (qi >= kstart) {
            // --- scores ---
            float tilemax = -1e30f;
            for (int kk = 0; kk < 32; kk++) {
                float a0 = 0.f, a1 = 0.f, a2 = 0.f, a3 = 0.f;
#pragma unroll
                for (int j = 0; j < 64; j += 4) {
                    float4 kv = *(const float4*)&Ks[kk][j];
                    a0 = fmaf(q[j],     kv.x, a0);
                    a1 = fmaf(q[j + 1], kv.y, a1);
                    a2 = fmaf(q[j + 2], kv.z, a2);
                    a3 = fmaf(q[j + 3], kv.w, a3);
                }
                float sv = ((a0 + a1) + (a2 + a3)) * scale;
                sv = (kstart + kk <= qi) ? sv : -1e30f;
                tilemax = fmaxf(tilemax, sv);
                Ss[r][kk] = sv;
            }
            // --- online softmax update ---
            float newm = fmaxf(mrun, tilemax);
            float f = __expf(mrun - newm);
            l *= f;
#pragma unroll
            for (int j = 0; j < 64; j++) o[j] *= f;

            for (int kk = 0; kk < 32; kk++) {
                float pk = __expf(Ss[r][kk] - newm);
                l += pk;
#pragma unroll
                for (int j = 0; j < 64; j += 4) {
                    float4 vv = *(const float4*)&Vs[kk][j];
                    o[j]     = fmaf(pk, vv.x, o[j]);
                    o[j + 1] = fmaf(pk, vv.y, o[j + 1]);
                    o[j + 2] = fmaf(pk, vv.z, o[j + 2]);
                    o[j + 3] = fmaf(pk, vv.w, o[j + 3]);
                }
            }
            mrun = newm;
        }
        __syncthreads();
    }

    float invl = 1.0f / l;
    float* optr = g_att + (size_t)(b * SEQ + qi) * D_MODEL + hoff;
#pragma unroll
    for (int j = 0; j < 64; j += 4) {
        float4 v4 = make_float4(o[j] * invl, o[j + 1] * invl,
                                o[j + 2] * invl, o[j + 3] * invl);
        *(float4*)(optr + j) = v4;
    }
}

// ---------------------------------------------------------------------------
extern "C" void kernel_launch(void* const* d_in, const int* in_sizes, int n_in,
                              void* d_out, int out_size)
{
    const float* x  = (const float*)d_in[0];
    const float* Wq = (const float*)d_in[1];
    const float* Wk = (const float*)d_in[2];
    const float* Wv = (const float*)d_in[3];
    const float* Wo = (const float*)d_in[4];
    float* out = (float*)d_out;

    float *q, *k, *v, *att;
    cudaGetSymbolAddress((void**)&q,   g_q);
    cudaGetSymbolAddress((void**)&k,   g_k);
    cudaGetSymbolAddress((void**)&v,   g_v);
    cudaGetSymbolAddress((void**)&att, g_att);

    dim3 ggrid(D_MODEL / 64, M_ROWS / 128);   // (16, 64)

    gemm_nt_kernel<<<ggrid, 256>>>(x, Wq, q, M_ROWS, D_MODEL, D_MODEL);
    gemm_nt_kernel<<<ggrid, 256>>>(x, Wk, k, M_ROWS, D_MODEL, D_MODEL);
    gemm_nt_kernel<<<ggrid, 256>>>(x, Wv, v, M_ROWS, D_MODEL, D_MODEL);

    const int rope_total = M_ROWS * N_HEADS * 32;
    rope_kernel<<<(rope_total + 255) / 256, 256>>>();

    flash_kernel<<<dim3(SEQ / 128, N_HEADS, BATCH), 128>>>();

    gemm_nt_kernel<<<ggrid, 256>>>(att, Wo, out, M_ROWS, D_MODEL, D_MODEL);
}

// round 3
// speedup vs baseline: 1.2940x; 1.2940x over previous
#include <cuda_runtime.h>
#include <math.h>
#include <stdint.h>

#define D_MODEL 1024
#define N_HEADS 16
#define HEAD_DIM 64
#define BATCH 4
#define SEQ 2048
#define M_ROWS (BATCH * SEQ)   // 8192

// Scratch (allocation-free rule: __device__ globals)
__device__ float g_q[M_ROWS * D_MODEL];
__device__ float g_k[M_ROWS * D_MODEL];
__device__ float g_v[M_ROWS * D_MODEL];
__device__ float g_att[M_ROWS * D_MODEL];
__device__ float2 g_rope[SEQ * 32];   // (cos, sin) per (t, d)

// ---------------------------------------------------------------------------
// tf32 helpers
// ---------------------------------------------------------------------------
__device__ __forceinline__ void split_tf32(float x, uint32_t& hi, uint32_t& lo)
{
    uint32_t h;
    asm("cvt.rna.tf32.f32 %0, %1;" : "=r"(h) : "f"(x));
    float l = x - __uint_as_float(h);
    uint32_t lw;
    asm("cvt.rna.tf32.f32 %0, %1;" : "=r"(lw) : "f"(l));
    hi = h; lo = lw;
}

#define MMA_TF32(C, A, B)                                                     \
    asm volatile(                                                             \
        "mma.sync.aligned.m16n8k8.row.col.f32.tf32.tf32.f32 "                 \
        "{%0,%1,%2,%3}, {%4,%5,%6,%7}, {%8,%9}, {%0,%1,%2,%3};"               \
        : "+f"(C[0]), "+f"(C[1]), "+f"(C[2]), "+f"(C[3])                      \
        : "r"(A[0]), "r"(A[1]), "r"(A[2]), "r"(A[3]), "r"(B[0]), "r"(B[1]))

// ---------------------------------------------------------------------------
// TF32 tensor-core GEMM with 3xTF32 compensation.
// C[M,N] = A[M,K] @ W[N,K]^T. Block tile 128x64, K-step 32, 256 threads.
// 8 warps: 4 (m) x 2 (n); warp tile 32x32 = 2 x 4 m16n8k8 fragments.
// Smem stores tiles in fragment-permuted order: A frag = one LDS.128,
// B frag = one LDS.64, both conflict-free.
// ---------------------------------------------------------------------------
#define BM 128
#define BN 64
#define BK 32

__global__ __launch_bounds__(256) void gemm_tf32_kernel(
    const float* __restrict__ A, const float* __restrict__ W,
    float* __restrict__ C, int M, int N, int K)
{
    __shared__ float As[BM * BK];   // ((tm*4+tk)*32 + lane)*4 + slot
    __shared__ float Bs[BN * BK];   // ((tn*4+tk)*32 + lane)*2 + slot

    const int tid  = threadIdx.x;
    const int lane = tid & 31;
    const int warp = tid >> 5;
    const int wm   = warp & 3;      // 0..3, 32 rows each
    const int wn   = warp >> 2;     // 0..1, 32 cols each
    const int row0 = blockIdx.y * BM;
    const int col0 = blockIdx.x * BN;

    float c[2][4][4] = {};

    for (int k0 = 0; k0 < K; k0 += BK) {
        // -- A tile 128x32: 1024 float4 global loads, scatter to permuted smem
#pragma unroll
        for (int it = 0; it < 4; it++) {
            int idx = tid + it * 256;
            int m   = idx >> 3;
            int kq  = idx & 7;              // k quad: k = kq*4 + j
            float4 v = *(const float4*)&A[(size_t)(row0 + m) * K + k0 + kq * 4];
            int tm = m >> 4;
            int tk = kq >> 1;
            int slot_base = ((m >> 3) & 1) + ((kq & 1) << 1);
            int lbase = (m & 7) << 2;
            float vv[4] = {v.x, v.y, v.z, v.w};
#pragma unroll
            for (int j = 0; j < 4; j++)
                As[((tm * 4 + tk) * 32 + lbase + j) * 4 + slot_base] = vv[j];
        }
        // -- W tile 64x32: 512 float4 loads
#pragma unroll
        for (int it = 0; it < 2; it++) {
            int idx = tid + it * 256;
            int n   = idx >> 3;
            int kq  = idx & 7;
            float4 v = *(const float4*)&W[(size_t)(col0 + n) * K + k0 + kq * 4];
            int tn = n >> 3;
            int tk = kq >> 1;
            int slot = kq & 1;
            int lbase = (n & 7) << 2;
            float vv[4] = {v.x, v.y, v.z, v.w};
#pragma unroll
            for (int j = 0; j < 4; j++)
                Bs[((tn * 4 + tk) * 32 + lbase + j) * 2 + slot] = vv[j];
        }
        __syncthreads();

#pragma unroll
        for (int tk = 0; tk < 4; tk++) {
            uint32_t ahi[2][4], alo[2][4];
#pragma unroll
            for (int mf = 0; mf < 2; mf++) {
                int tm = wm * 2 + mf;
                float4 a = *(const float4*)&As[((tm * 4 + tk) * 32 + lane) * 4];
                split_tf32(a.x, ahi[mf][0], alo[mf][0]);
                split_tf32(a.y, ahi[mf][1], alo[mf][1]);
                split_tf32(a.z, ahi[mf][2], alo[mf][2]);
                split_tf32(a.w, ahi[mf][3], alo[mf][3]);
            }
            uint32_t bhi[4][2], blo[4][2];
#pragma unroll
            for (int nf = 0; nf < 4; nf++) {
                int tn = wn * 4 + nf;
                float2 b = *(const float2*)&Bs[((tn * 4 + tk) * 32 + lane) * 2];
                split_tf32(b.x, bhi[nf][0], blo[nf][0]);
                split_tf32(b.y, bhi[nf][1], blo[nf][1]);
            }
#pragma unroll
            for (int mf = 0; mf < 2; mf++)
#pragma unroll
                for (int nf = 0; nf < 4; nf++) {
                    MMA_TF32(c[mf][nf], ahi[mf], bhi[nf]);
                    MMA_TF32(c[mf][nf], ahi[mf], blo[nf]);
                    MMA_TF32(c[mf][nf], alo[mf], bhi[nf]);
                }
        }
        __syncthreads();
    }

    // Epilogue: c0,c1 -> (row, col..col+1); c2,c3 -> (row+8, ...)
    const int r  = lane >> 2;
    const int cc = (lane & 3) * 2;
#pragma unroll
    for (int mf = 0; mf < 2; mf++)
#pragma unroll
        for (int nf = 0; nf < 4; nf++) {
            int row = row0 + wm * 32 + mf * 16 + r;
            int col = col0 + wn * 32 + nf * 8 + cc;
            *(float2*)&C[(size_t)row * N + col] =
                make_float2(c[mf][nf][0], c[mf][nf][1]);
            *(float2*)&C[(size_t)(row + 8) * N + col] =
                make_float2(c[mf][nf][2], c[mf][nf][3]);
        }
}

// ---------------------------------------------------------------------------
// RoPE: fp64-accurate table (65K entries), then memory-bound apply.
// ---------------------------------------------------------------------------
__global__ void rope_table_kernel()
{
    int idx = blockIdx.x * blockDim.x + threadIdx.x;
    if (idx >= SEQ * 32) return;
    int t = idx >> 5;
    int d = idx & 31;
    double inv = pow(10000.0, -(double)d / 32.0);
    double sn, cs;
    sincos((double)t * inv, &sn, &cs);
    g_rope[idx] = make_float2((float)cs, (float)sn);
}

__global__ void rope_apply_kernel()
{
    int idx = blockIdx.x * blockDim.x + threadIdx.x;
    const int total = M_ROWS * N_HEADS * 32;
    if (idx >= total) return;

    int d  = idx & 31;
    int h  = (idx >> 5) & (N_HEADS - 1);
    int bt = idx >> 9;
    int t  = bt & (SEQ - 1);

    float2 cs = g_rope[t * 32 + d];
    float c = cs.x, s = cs.y;

    size_t base = (size_t)bt * D_MODEL + h * HEAD_DIM + d;
    float x1 = g_q[base], x2 = g_q[base + 32];
    g_q[base]      = x1 * c - x2 * s;
    g_q[base + 32] = x2 * c + x1 * s;
    x1 = g_k[base]; x2 = g_k[base + 32];
    g_k[base]      = x1 * c - x2 * s;
    g_k[base + 32] = x2 * c + x1 * s;
}

// ---------------------------------------------------------------------------
// Causal flash attention (fp32 SIMT). Block: 128 query rows, 128 threads.
// ---------------------------------------------------------------------------
__global__ __launch_bounds__(128) void flash_kernel()
{
    __shared__ float Ks[32][64];
    __shared__ float Vs[32][64];
    __shared__ float Ss[128][33];

    const int r  = threadIdx.x;
    const int q0 = blockIdx.x * 128;
    const int h  = blockIdx.y;
    const int b  = blockIdx.z;
    const int qi = q0 + r;
    const int hoff = h * HEAD_DIM;

    const float* qptr  = g_q + (size_t)(b * SEQ + qi) * D_MODEL + hoff;
    const float* kbase = g_k + (size_t)(b * SEQ) * D_MODEL + hoff;
    const float* vbase = g_v + (size_t)(b * SEQ) * D_MODEL + hoff;

    float q[64];
#pragma unroll
    for (int j = 0; j < 64; j += 4) {
        float4 t4 = *(const float4*)(qptr + j);
        q[j] = t4.x; q[j + 1] = t4.y; q[j + 2] = t4.z; q[j + 3] = t4.w;
    }

    float o[64];
#pragma unroll
    for (int j = 0; j < 64; j++) o[j] = 0.0f;
    float mrun = -1e30f, l = 0.0f;

    const int ntiles = q0 / 32 + 4;
    const float scale = 0.125f;

    for (int kt = 0; kt < ntiles; kt++) {
        const int kstart = kt * 32;
#pragma unroll
        for (int it = 0; it < 4; it++) {
            int i = r + it * 128;
            int rowk = i >> 4;
            int c4 = (i & 15) * 4;
            size_t goff = (size_t)(kstart + rowk) * D_MODEL + c4;
            *(float4*)&Ks[rowk][c4] = *(const float4*)(kbase + goff);
            *(float4*)&Vs[rowk][c4] = *(const float4*)(vbase + goff);
        }
        __syncthreads();

        if (qi >= kstart) {
            float tilemax = -1e30f;
            for (int kk = 0; kk < 32; kk++) {
                float a0 = 0.f, a1 = 0.f, a2 = 0.f, a3 = 0.f;
#pragma unroll
                for (int j = 0; j < 64; j += 4) {
                    float4 kv = *(const float4*)&Ks[kk][j];
                    a0 = fmaf(q[j],     kv.x, a0);
                    a1 = fmaf(q[j + 1], kv.y, a1);
                    a2 = fmaf(q[j + 2], kv.z, a2);
                    a3 = fmaf(q[j + 3], kv.w, a3);
                }
                float sv = ((a0 + a1) + (a2 + a3)) * scale;
                sv = (kstart + kk <= qi) ? sv : -1e30f;
                tilemax = fmaxf(tilemax, sv);
                Ss[r][kk] = sv;
            }
            float newm = fmaxf(mrun, tilemax);
            float f = __expf(mrun - newm);
            l *= f;
#pragma unroll
            for (int j = 0; j < 64; j++) o[j] *= f;

            for (int kk = 0; kk < 32; kk++) {
                float pk = __expf(Ss[r][kk] - newm);
                l += pk;
#pragma unroll
                for (int j = 0; j < 64; j += 4) {
                    float4 vv = *(const float4*)&Vs[kk][j];
                    o[j]     = fmaf(pk, vv.x, o[j]);
                    o[j + 1] = fmaf(pk, vv.y, o[j + 1]);
                    o[j + 2] = fmaf(pk, vv.z, o[j + 2]);
                    o[j + 3] = fmaf(pk, vv.w, o[j + 3]);
                }
            }
            mrun = newm;
        }
        __syncthreads();
    }

    float invl = 1.0f / l;
    float* optr = g_att + (size_t)(b * SEQ + qi) * D_MODEL + hoff;
#pragma unroll
    for (int j = 0; j < 64; j += 4) {
        float4 v4 = make_float4(o[j] * invl, o[j + 1] * invl,
                                o[j + 2] * invl, o[j + 3] * invl);
        *(float4*)(optr + j) = v4;
    }
}

// ---------------------------------------------------------------------------
extern "C" void kernel_launch(void* const* d_in, const int* in_sizes, int n_in,
                              void* d_out, int out_size)
{
    const float* x  = (const float*)d_in[0];
    const float* Wq = (const float*)d_in[1];
    const float* Wk = (const float*)d_in[2];
    const float* Wv = (const float*)d_in[3];
    const float* Wo = (const float*)d_in[4];
    float* out = (float*)d_out;

    float *q, *k, *v, *att;
    cudaGetSymbolAddress((void**)&q,   g_q);
    cudaGetSymbolAddress((void**)&k,   g_k);
    cudaGetSymbolAddress((void**)&v,   g_v);
    cudaGetSymbolAddress((void**)&att, g_att);

    dim3 ggrid(D_MODEL / BN, M_ROWS / BM);   // (16, 64)

    rope_table_kernel<<<(SEQ * 32 + 255) / 256, 256>>>();

    gemm_tf32_kernel<<<ggrid, 256>>>(x, Wq, q, M_ROWS, D_MODEL, D_MODEL);
    gemm_tf32_kernel<<<ggrid, 256>>>(x, Wk, k, M_ROWS, D_MODEL, D_MODEL);
    gemm_tf32_kernel<<<ggrid, 256>>>(x, Wv, v, M_ROWS, D_MODEL, D_MODEL);

    const int rope_total = M_ROWS * N_HEADS * 32;
    rope_apply_kernel<<<(rope_total + 255) / 256, 256>>>();

    flash_kernel<<<dim3(SEQ / 128, N_HEADS, BATCH), 128>>>();

    gemm_tf32_kernel<<<ggrid, 256>>>(att, Wo, out, M_ROWS, D_MODEL, D_MODEL);
}

// round 4
// speedup vs baseline: 1.4536x; 1.1233x over previous
#include <cuda_runtime.h>
#include <math.h>
#include <stdint.h>

#define D_MODEL 1024
#define N_HEADS 16
#define HEAD_DIM 64
#define BATCH 4
#define SEQ 2048
#define M_ROWS (BATCH * SEQ)   // 8192

// Scratch (allocation-free rule: __device__ globals)
__device__ float g_q[M_ROWS * D_MODEL];
__device__ float g_k[M_ROWS * D_MODEL];
__device__ float g_v[M_ROWS * D_MODEL];
__device__ float g_att[M_ROWS * D_MODEL];
__device__ float2 g_rope[SEQ * 32];   // (cos, sin) per (t, d)

// ---------------------------------------------------------------------------
// tf32 helpers
// ---------------------------------------------------------------------------
__device__ __forceinline__ void split_tf32(float x, uint32_t& hi, uint32_t& lo)
{
    uint32_t h;
    asm("cvt.rna.tf32.f32 %0, %1;" : "=r"(h) : "f"(x));
    float l = x - __uint_as_float(h);
    uint32_t lw;
    asm("cvt.rna.tf32.f32 %0, %1;" : "=r"(lw) : "f"(l));
    hi = h; lo = lw;
}

__device__ __forceinline__ void mma_tf32(float* C, const uint32_t* A, const uint32_t* B)
{
    asm volatile(
        "mma.sync.aligned.m16n8k8.row.col.f32.tf32.tf32.f32 "
        "{%0,%1,%2,%3}, {%4,%5,%6,%7}, {%8,%9}, {%0,%1,%2,%3};"
        : "+f"(C[0]), "+f"(C[1]), "+f"(C[2]), "+f"(C[3])
        : "r"(A[0]), "r"(A[1]), "r"(A[2]), "r"(A[3]), "r"(B[0]), "r"(B[1]));
}

// ---------------------------------------------------------------------------
// TF32 GEMM, 3xTF32 compensation, hi/lo PRE-SPLIT into smem at fill time.
// C[M,N] = A[M,K] @ W[N,K]^T. Block 128x64, K-step 32, 256 threads.
// ---------------------------------------------------------------------------
#define BM 128
#define BN 64
#define BK 32

__global__ __launch_bounds__(256) void gemm_tf32_kernel(
    const float* __restrict__ A, const float* __restrict__ W,
    float* __restrict__ C, int M, int N, int K)
{
    __shared__ float Ashi[BM * BK], Aslo[BM * BK];   // ((tm*4+tk)*32+lane)*4+slot
    __shared__ float Bshi[BN * BK], Bslo[BN * BK];   // ((tn*4+tk)*32+lane)*2+slot

    const int tid  = threadIdx.x;
    const int lane = tid & 31;
    const int warp = tid >> 5;
    const int wm   = warp & 3;
    const int wn   = warp >> 2;
    const int row0 = blockIdx.y * BM;
    const int col0 = blockIdx.x * BN;

    float c[2][4][4] = {};

    for (int k0 = 0; k0 < K; k0 += BK) {
#pragma unroll
        for (int it = 0; it < 4; it++) {
            int idx = tid + it * 256;
            int m   = idx >> 3;
            int kq  = idx & 7;
            float4 v = *(const float4*)&A[(size_t)(row0 + m) * K + k0 + kq * 4];
            int tm = m >> 4;
            int tk = kq >> 1;
            int slot_base = ((m >> 3) & 1) + ((kq & 1) << 1);
            int lbase = (m & 7) << 2;
            float vv[4] = {v.x, v.y, v.z, v.w};
#pragma unroll
            for (int j = 0; j < 4; j++) {
                uint32_t h, l;
                split_tf32(vv[j], h, l);
                int a = ((tm * 4 + tk) * 32 + lbase + j) * 4 + slot_base;
                Ashi[a] = __uint_as_float(h);
                Aslo[a] = __uint_as_float(l);
            }
        }
#pragma unroll
        for (int it = 0; it < 2; it++) {
            int idx = tid + it * 256;
            int n   = idx >> 3;
            int kq  = idx & 7;
            float4 v = *(const float4*)&W[(size_t)(col0 + n) * K + k0 + kq * 4];
            int tn = n >> 3;
            int tk = kq >> 1;
            int slot = kq & 1;
            int lbase = (n & 7) << 2;
            float vv[4] = {v.x, v.y, v.z, v.w};
#pragma unroll
            for (int j = 0; j < 4; j++) {
                uint32_t h, l;
                split_tf32(vv[j], h, l);
                int a = ((tn * 4 + tk) * 32 + lbase + j) * 2 + slot;
                Bshi[a] = __uint_as_float(h);
                Bslo[a] = __uint_as_float(l);
            }
        }
        __syncthreads();

#pragma unroll
        for (int tk = 0; tk < 4; tk++) {
            uint32_t ahi[2][4], alo[2][4];
#pragma unroll
            for (int mf = 0; mf < 2; mf++) {
                int tm = wm * 2 + mf;
                int a = ((tm * 4 + tk) * 32 + lane) * 4;
                float4 h4 = *(const float4*)&Ashi[a];
                float4 l4 = *(const float4*)&Aslo[a];
                ahi[mf][0] = __float_as_uint(h4.x); ahi[mf][1] = __float_as_uint(h4.y);
                ahi[mf][2] = __float_as_uint(h4.z); ahi[mf][3] = __float_as_uint(h4.w);
                alo[mf][0] = __float_as_uint(l4.x); alo[mf][1] = __float_as_uint(l4.y);
                alo[mf][2] = __float_as_uint(l4.z); alo[mf][3] = __float_as_uint(l4.w);
            }
            uint32_t bhi[4][2], blo[4][2];
#pragma unroll
            for (int nf = 0; nf < 4; nf++) {
                int tn = wn * 4 + nf;
                int a = ((tn * 4 + tk) * 32 + lane) * 2;
                float2 h2 = *(const float2*)&Bshi[a];
                float2 l2 = *(const float2*)&Bslo[a];
                bhi[nf][0] = __float_as_uint(h2.x); bhi[nf][1] = __float_as_uint(h2.y);
                blo[nf][0] = __float_as_uint(l2.x); blo[nf][1] = __float_as_uint(l2.y);
            }
#pragma unroll
            for (int mf = 0; mf < 2; mf++)
#pragma unroll
                for (int nf = 0; nf < 4; nf++) {
                    mma_tf32(c[mf][nf], ahi[mf], bhi[nf]);
                    mma_tf32(c[mf][nf], ahi[mf], blo[nf]);
                    mma_tf32(c[mf][nf], alo[mf], bhi[nf]);
                }
        }
        __syncthreads();
    }

    const int r  = lane >> 2;
    const int cc = (lane & 3) * 2;
#pragma unroll
    for (int mf = 0; mf < 2; mf++)
#pragma unroll
        for (int nf = 0; nf < 4; nf++) {
            int row = row0 + wm * 32 + mf * 16 + r;
            int col = col0 + wn * 32 + nf * 8 + cc;
            *(float2*)&C[(size_t)row * N + col] =
                make_float2(c[mf][nf][0], c[mf][nf][1]);
            *(float2*)&C[(size_t)(row + 8) * N + col] =
                make_float2(c[mf][nf][2], c[mf][nf][3]);
        }
}

// ---------------------------------------------------------------------------
// RoPE table + apply
// ---------------------------------------------------------------------------
__global__ void rope_table_kernel()
{
    int idx = blockIdx.x * blockDim.x + threadIdx.x;
    if (idx >= SEQ * 32) return;
    int t = idx >> 5;
    int d = idx & 31;
    double inv = pow(10000.0, -(double)d / 32.0);
    double sn, cs;
    sincos((double)t * inv, &sn, &cs);
    g_rope[idx] = make_float2((float)cs, (float)sn);
}

__global__ void rope_apply_kernel()
{
    int idx = blockIdx.x * blockDim.x + threadIdx.x;
    const int total = M_ROWS * N_HEADS * 32;
    if (idx >= total) return;

    int d  = idx & 31;
    int h  = (idx >> 5) & (N_HEADS - 1);
    int bt = idx >> 9;
    int t  = bt & (SEQ - 1);

    float2 cs = g_rope[t * 32 + d];
    float c = cs.x, s = cs.y;

    size_t base = (size_t)bt * D_MODEL + h * HEAD_DIM + d;
    float x1 = g_q[base], x2 = g_q[base + 32];
    g_q[base]      = x1 * c - x2 * s;
    g_q[base + 32] = x2 * c + x1 * s;
    x1 = g_k[base]; x2 = g_k[base + 32];
    g_k[base]      = x1 * c - x2 * s;
    g_k[base + 32] = x2 * c + x1 * s;
}

// ---------------------------------------------------------------------------
// Tensor-core causal flash attention.
// Block: 64 query rows (one b,h), 128 threads = 4 warps (16 rows each).
// Key tiles of 64. QK^T and P*V via m16n8k8 tf32 with 3xTF32 compensation.
// K/V pre-split hi/lo into fragment-permuted dynamic smem.
// Q pre-split (with 1/8 scale folded) into registers.
// ---------------------------------------------------------------------------
#define FR 66            // padded frag stride (64 + 2)
#define SM_KHI 0
#define SM_KLO (64 * FR)
#define SM_VHI (128 * FR)
#define SM_VLO (192 * FR)
#define SM_P   (256 * FR)            // 16896
#define FLASH_SMEM_FLOATS (256 * FR + 4096)
#define FLASH_SMEM_BYTES  (FLASH_SMEM_FLOATS * 4)

__global__ __launch_bounds__(128) void flash_tc_kernel()
{
    extern __shared__ float sm[];

    const int tid  = threadIdx.x;
    const int lane = tid & 31;
    const int w    = tid >> 5;
    const int qt   = gridDim.x - 1 - blockIdx.x;   // big blocks first
    const int q0   = qt * 64;
    const int h    = blockIdx.y;
    const int b    = blockIdx.z;

    const int rquad = lane >> 2;     // 0..7
    const int lmod  = lane & 3;
    const int rowA  = q0 + w * 16 + rquad;
    const int rowB  = rowA + 8;

    const float* kbase = g_k + (size_t)(b * SEQ) * D_MODEL + h * HEAD_DIM;
    const float* vbase = g_v + (size_t)(b * SEQ) * D_MODEL + h * HEAD_DIM;

    // ---- Q fragments in registers, scaled by 1/8 (exact), pre-split ----
    uint32_t qhi[8][4], qlo[8][4];
    {
        const float* qr0 = g_q + (size_t)(b * SEQ + rowA) * D_MODEL + h * HEAD_DIM;
        const float* qr1 = qr0 + 8 * D_MODEL;
#pragma unroll
        for (int kf = 0; kf < 8; kf++) {
            float a0 = qr0[kf * 8 + lmod]     * 0.125f;
            float a1 = qr1[kf * 8 + lmod]     * 0.125f;
            float a2 = qr0[kf * 8 + lmod + 4] * 0.125f;
            float a3 = qr1[kf * 8 + lmod + 4] * 0.125f;
            split_tf32(a0, qhi[kf][0], qlo[kf][0]);
            split_tf32(a1, qhi[kf][1], qlo[kf][1]);
            split_tf32(a2, qhi[kf][2], qlo[kf][2]);
            split_tf32(a3, qhi[kf][3], qlo[kf][3]);
        }
    }

    float oacc[8][4] = {};
    float mA = -1e30f, mB = -1e30f;
    float lA = 0.0f,   lB = 0.0f;

    const int ntiles = qt + 1;

    for (int kt = 0; kt < ntiles; kt++) {
        const int kstart = kt * 64;
        const bool diag = (kt == ntiles - 1);

        // ---- fill K/V tile: split hi/lo into permuted smem ----
        // K frag f = nf*8+kf (nf = key/8, kf = dim/8); V frag f = kf*8+nf.
#pragma unroll
        for (int pass = 0; pass < 8; pass++) {
            int t  = tid + pass * 128;
            int n  = t >> 4;          // row in tile (key)
            int q4 = t & 15;          // float4 index over dims
            size_t goff = (size_t)(kstart + n) * D_MODEL + q4 * 4;
            float4 kv = *(const float4*)(kbase + goff);
            float4 vv = *(const float4*)(vbase + goff);
            int kf   = q4 >> 1;
            int slot = q4 & 1;
            // K: lane = (n%8)*4 + j
            int kaddr = ((n >> 3) * 8 + kf) * FR + ((n & 7) << 3) + slot;
            float kv4[4] = {kv.x, kv.y, kv.z, kv.w};
            float vv4[4] = {vv.x, vv.y, vv.z, vv.w};
#pragma unroll
            for (int j = 0; j < 4; j++) {
                uint32_t hh, ll;
                split_tf32(kv4[j], hh, ll);
                sm[SM_KHI + kaddr + j * 2] = __uint_as_float(hh);
                sm[SM_KLO + kaddr + j * 2] = __uint_as_float(ll);
            }
            // V: element (key s=n, dim d=4q4+j): f=(s/8)*8 + d/8,
            //    lane = (d%8)*4 + (s&3), slot = (s>>2)&1
            int vf    = (n >> 3) * 8 + (q4 >> 1);
            int vslot = (n >> 2) & 1;
            int dlo   = (q4 & 1) * 4;   // d%8 base
#pragma unroll
            for (int j = 0; j < 4; j++) {
                uint32_t hh, ll;
                split_tf32(vv4[j], hh, ll);
                int vaddr = vf * FR + ((dlo + j) * 4 + (n & 3)) * 2 + vslot;
                sm[SM_VHI + vaddr] = __uint_as_float(hh);
                sm[SM_VLO + vaddr] = __uint_as_float(ll);
            }
        }
        __syncthreads();

        // ---- S = Qs @ K^T (3xTF32) ----
        float c[8][4] = {};
#pragma unroll
        for (int kf = 0; kf < 8; kf++) {
#pragma unroll
            for (int nf = 0; nf < 8; nf++) {
                int a = (nf * 8 + kf) * FR + lane * 2;
                float2 h2 = *(const float2*)&sm[SM_KHI + a];
                float2 l2 = *(const float2*)&sm[SM_KLO + a];
                uint32_t bh[2] = {__float_as_uint(h2.x), __float_as_uint(h2.y)};
                uint32_t bl[2] = {__float_as_uint(l2.x), __float_as_uint(l2.y)};
                mma_tf32(c[nf], qhi[kf], bh);
                mma_tf32(c[nf], qhi[kf], bl);
                mma_tf32(c[nf], qlo[kf], bh);
            }
        }

        // ---- causal mask (diagonal tile only) ----
        if (diag) {
#pragma unroll
            for (int nf = 0; nf < 8; nf++) {
                int col = kstart + nf * 8 + 2 * lmod;
                if (col     > rowA) c[nf][0] = -1e30f;
                if (col + 1 > rowA) c[nf][1] = -1e30f;
                if (col     > rowB) c[nf][2] = -1e30f;
                if (col + 1 > rowB) c[nf][3] = -1e30f;
            }
        }

        // ---- online softmax ----
        float tmA = -1e30f, tmB = -1e30f;
#pragma unroll
        for (int nf = 0; nf < 8; nf++) {
            tmA = fmaxf(tmA, fmaxf(c[nf][0], c[nf][1]));
            tmB = fmaxf(tmB, fmaxf(c[nf][2], c[nf][3]));
        }
        tmA = fmaxf(tmA, __shfl_xor_sync(0xffffffffu, tmA, 1));
        tmA = fmaxf(tmA, __shfl_xor_sync(0xffffffffu, tmA, 2));
        tmB = fmaxf(tmB, __shfl_xor_sync(0xffffffffu, tmB, 1));
        tmB = fmaxf(tmB, __shfl_xor_sync(0xffffffffu, tmB, 2));

        float nmA = fmaxf(mA, tmA), nmB = fmaxf(mB, tmB);
        float fA = __expf(mA - nmA), fB = __expf(mB - nmB);
        mA = nmA; mB = nmB;
        lA *= fA; lB *= fB;
#pragma unroll
        for (int nf = 0; nf < 8; nf++) {
            oacc[nf][0] *= fA; oacc[nf][1] *= fA;
            oacc[nf][2] *= fB; oacc[nf][3] *= fB;
        }

        // p = exp(s - m), accumulate l, stage P to smem (C-layout)
#pragma unroll
        for (int nf = 0; nf < 8; nf++) {
            float p0 = __expf(c[nf][0] - mA);
            float p1 = __expf(c[nf][1] - mA);
            float p2 = __expf(c[nf][2] - mB);
            float p3 = __expf(c[nf][3] - mB);
            lA += p0 + p1;
            lB += p2 + p3;
            *(float4*)&sm[SM_P + ((w * 8 + nf) * 32 + lane) * 4] =
                make_float4(p0, p1, p2, p3);
        }
        __syncwarp();

        // ---- O += P @ V (3xTF32) ----
        const int pA0base = (lane >> 2) * 4 + ((lane & 3) >> 1);
        const int pbit    = lane & 1;
#pragma unroll
        for (int kf = 0; kf < 8; kf++) {
            int fb = (w * 8 + kf) * 32;
            float p0 = sm[SM_P + (fb + pA0base) * 4 + pbit];
            float p1 = sm[SM_P + (fb + pA0base) * 4 + pbit + 2];
            float p2 = sm[SM_P + (fb + pA0base + 2) * 4 + pbit];
            float p3 = sm[SM_P + (fb + pA0base + 2) * 4 + pbit + 2];
            uint32_t phi[4], plo[4];
            split_tf32(p0, phi[0], plo[0]);
            split_tf32(p1, phi[1], plo[1]);
            split_tf32(p2, phi[2], plo[2]);
            split_tf32(p3, phi[3], plo[3]);
#pragma unroll
            for (int nf = 0; nf < 8; nf++) {
                int a = (kf * 8 + nf) * FR + lane * 2;
                float2 h2 = *(const float2*)&sm[SM_VHI + a];
                float2 l2 = *(const float2*)&sm[SM_VLO + a];
                uint32_t bh[2] = {__float_as_uint(h2.x), __float_as_uint(h2.y)};
                uint32_t bl[2] = {__float_as_uint(l2.x), __float_as_uint(l2.y)};
                mma_tf32(oacc[nf], phi, bh);
                mma_tf32(oacc[nf], phi, bl);
                mma_tf32(oacc[nf], plo, bh);
            }
        }
        __syncthreads();
    }

    // ---- finalize: reduce l across quad, normalize, write ----
    lA += __shfl_xor_sync(0xffffffffu, lA, 1);
    lA += __shfl_xor_sync(0xffffffffu, lA, 2);
    lB += __shfl_xor_sync(0xffffffffu, lB, 1);
    lB += __shfl_xor_sync(0xffffffffu, lB, 2);
    float iA = 1.0f / lA, iB = 1.0f / lB;

    float* outA = g_att + (size_t)(b * SEQ + rowA) * D_MODEL + h * HEAD_DIM;
    float* outB = g_att + (size_t)(b * SEQ + rowB) * D_MODEL + h * HEAD_DIM;
#pragma unroll
    for (int nf = 0; nf < 8; nf++) {
        int col = nf * 8 + 2 * lmod;
        *(float2*)(outA + col) = make_float2(oacc[nf][0] * iA, oacc[nf][1] * iA);
        *(float2*)(outB + col) = make_float2(oacc[nf][2] * iB, oacc[nf][3] * iB);
    }
}

// ---------------------------------------------------------------------------
extern "C" void kernel_launch(void* const* d_in, const int* in_sizes, int n_in,
                              void* d_out, int out_size)
{
    const float* x  = (const float*)d_in[0];
    const float* Wq = (const float*)d_in[1];
    const float* Wk = (const float*)d_in[2];
    const float* Wv = (const float*)d_in[3];
    const float* Wo = (const float*)d_in[4];
    float* out = (float*)d_out;

    float *q, *k, *v, *att;
    cudaGetSymbolAddress((void**)&q,   g_q);
    cudaGetSymbolAddress((void**)&k,   g_k);
    cudaGetSymbolAddress((void**)&v,   g_v);
    cudaGetSymbolAddress((void**)&att, g_att);

    cudaFuncSetAttribute(flash_tc_kernel,
                         cudaFuncAttributeMaxDynamicSharedMemorySize,
                         FLASH_SMEM_BYTES);

    dim3 ggrid(D_MODEL / BN, M_ROWS / BM);   // (16, 64)

    rope_table_kernel<<<(SEQ * 32 + 255) / 256, 256>>>();

    gemm_tf32_kernel<<<ggrid, 256>>>(x, Wq, q, M_ROWS, D_MODEL, D_MODEL);
    gemm_tf32_kernel<<<ggrid, 256>>>(x, Wk, k, M_ROWS, D_MODEL, D_MODEL);
    gemm_tf32_kernel<<<ggrid, 256>>>(x, Wv, v, M_ROWS, D_MODEL, D_MODEL);

    const int rope_total = M_ROWS * N_HEADS * 32;
    rope_apply_kernel<<<(rope_total + 255) / 256, 256>>>();

    flash_tc_kernel<<<dim3(SEQ / 64, N_HEADS, BATCH), 128, FLASH_SMEM_BYTES>>>();

    gemm_tf32_kernel<<<ggrid, 256>>>(att, Wo, out, M_ROWS, D_MODEL, D_MODEL);
}

// round 5
// speedup vs baseline: 1.7458x; 1.2010x over previous
#include <cuda_runtime.h>
#include <math.h>
#include <stdint.h>

#define D_MODEL 1024
#define N_HEADS 16
#define HEAD_DIM 64
#define BATCH 4
#define SEQ 2048
#define M_ROWS (BATCH * SEQ)   // 8192

// Scratch (allocation-free rule: __device__ globals)
__device__ float g_q[M_ROWS * D_MODEL];
__device__ float g_k[M_ROWS * D_MODEL];
__device__ float g_v[M_ROWS * D_MODEL];
__device__ float g_att[M_ROWS * D_MODEL];
__device__ float2 g_rope[SEQ * 32];   // (cos, sin) per (t, d)

// ---------------------------------------------------------------------------
// tf32 helpers
// ---------------------------------------------------------------------------
__device__ __forceinline__ void split_tf32(float x, uint32_t& hi, uint32_t& lo)
{
    uint32_t h;
    asm("cvt.rna.tf32.f32 %0, %1;" : "=r"(h) : "f"(x));
    float l = x - __uint_as_float(h);
    uint32_t lw;
    asm("cvt.rna.tf32.f32 %0, %1;" : "=r"(lw) : "f"(l));
    hi = h; lo = lw;
}

__device__ __forceinline__ void mma_tf32(float* C, const uint32_t* A, const uint32_t* B)
{
    asm volatile(
        "mma.sync.aligned.m16n8k8.row.col.f32.tf32.tf32.f32 "
        "{%0,%1,%2,%3}, {%4,%5,%6,%7}, {%8,%9}, {%0,%1,%2,%3};"
        : "+f"(C[0]), "+f"(C[1]), "+f"(C[2]), "+f"(C[3])
        : "r"(A[0]), "r"(A[1]), "r"(A[2]), "r"(A[3]), "r"(B[0]), "r"(B[1]));
}

// ---------------------------------------------------------------------------
// TF32 GEMM, 3xTF32 compensation. fp32 in smem (fragment-permuted layout),
// hi/lo split in registers at fragment load (amortized over 4 reuses).
// C[M,N] = A[M,K] @ W[N,K]^T. Block 128x128, K-step 32, 256 threads.
// 8 warps = 2(m) x 4(n); warp tile 64x32 = 4 x 4 m16n8k8 fragments.
// ---------------------------------------------------------------------------
#define BM 128
#define BN 128
#define BK 32

__global__ __launch_bounds__(256, 2) void gemm_tf32_kernel(
    const float* __restrict__ A, const float* __restrict__ W,
    float* __restrict__ C, int M, int N, int K)
{
    __shared__ float As[BM * BK];   // ((fa*4+tk)*32 + lane)*4 + slot
    __shared__ float Bs[BN * BK];   // ((tn*4+tk)*32 + lane)*2 + slot

    const int tid  = threadIdx.x;
    const int lane = tid & 31;
    const int warp = tid >> 5;
    const int wm   = warp & 1;      // 0..1, 64 rows each
    const int wn   = warp >> 1;     // 0..3, 32 cols each
    const int row0 = blockIdx.y * BM;
    const int col0 = blockIdx.x * BN;

    float c[4][4][4] = {};

    for (int k0 = 0; k0 < K; k0 += BK) {
        // -- A tile 128x32 (1024 float4), coalesced loads, permuted scatter
#pragma unroll
        for (int it = 0; it < 4; it++) {
            int idx = tid + it * 256;
            int m   = idx >> 3;
            int kq  = idx & 7;
            float4 v = *(const float4*)&A[(size_t)(row0 + m) * K + k0 + kq * 4];
            int fa = m >> 4;
            int tk = kq >> 1;
            int slot_base = ((m >> 3) & 1) + ((kq & 1) << 1);
            int lbase = (m & 7) << 2;
            float vv[4] = {v.x, v.y, v.z, v.w};
#pragma unroll
            for (int j = 0; j < 4; j++)
                As[((fa * 4 + tk) * 32 + lbase + j) * 4 + slot_base] = vv[j];
        }
        // -- W tile 128x32 (1024 float4)
#pragma unroll
        for (int it = 0; it < 4; it++) {
            int idx = tid + it * 256;
            int n   = idx >> 3;
            int kq  = idx & 7;
            float4 v = *(const float4*)&W[(size_t)(col0 + n) * K + k0 + kq * 4];
            int tn = n >> 3;
            int tk = kq >> 1;
            int slot = kq & 1;
            int lbase = (n & 7) << 2;
            float vv[4] = {v.x, v.y, v.z, v.w};
#pragma unroll
            for (int j = 0; j < 4; j++)
                Bs[((tn * 4 + tk) * 32 + lbase + j) * 2 + slot] = vv[j];
        }
        __syncthreads();

#pragma unroll
        for (int tk = 0; tk < 4; tk++) {
            uint32_t ahi[4][4], alo[4][4];
#pragma unroll
            for (int mf = 0; mf < 4; mf++) {
                int fa = wm * 4 + mf;
                float4 a = *(const float4*)&As[((fa * 4 + tk) * 32 + lane) * 4];
                split_tf32(a.x, ahi[mf][0], alo[mf][0]);
                split_tf32(a.y, ahi[mf][1], alo[mf][1]);
                split_tf32(a.z, ahi[mf][2], alo[mf][2]);
                split_tf32(a.w, ahi[mf][3], alo[mf][3]);
            }
            uint32_t bhi[4][2], blo[4][2];
#pragma unroll
            for (int nf = 0; nf < 4; nf++) {
                int tn = wn * 4 + nf;
                float2 b = *(const float2*)&Bs[((tn * 4 + tk) * 32 + lane) * 2];
                split_tf32(b.x, bhi[nf][0], blo[nf][0]);
                split_tf32(b.y, bhi[nf][1], blo[nf][1]);
            }
#pragma unroll
            for (int mf = 0; mf < 4; mf++)
#pragma unroll
                for (int nf = 0; nf < 4; nf++) {
                    mma_tf32(c[mf][nf], ahi[mf], bhi[nf]);
                    mma_tf32(c[mf][nf], ahi[mf], blo[nf]);
                    mma_tf32(c[mf][nf], alo[mf], bhi[nf]);
                }
        }
        __syncthreads();
    }

    const int r  = lane >> 2;
    const int cc = (lane & 3) * 2;
#pragma unroll
    for (int mf = 0; mf < 4; mf++)
#pragma unroll
        for (int nf = 0; nf < 4; nf++) {
            int row = row0 + wm * 64 + mf * 16 + r;
            int col = col0 + wn * 32 + nf * 8 + cc;
            *(float2*)&C[(size_t)row * N + col] =
                make_float2(c[mf][nf][0], c[mf][nf][1]);
            *(float2*)&C[(size_t)(row + 8) * N + col] =
                make_float2(c[mf][nf][2], c[mf][nf][3]);
        }
}

// ---------------------------------------------------------------------------
// RoPE table + apply
// ---------------------------------------------------------------------------
__global__ void rope_table_kernel()
{
    int idx = blockIdx.x * blockDim.x + threadIdx.x;
    if (idx >= SEQ * 32) return;
    int t = idx >> 5;
    int d = idx & 31;
    double inv = pow(10000.0, -(double)d / 32.0);
    double sn, cs;
    sincos((double)t * inv, &sn, &cs);
    g_rope[idx] = make_float2((float)cs, (float)sn);
}

__global__ void rope_apply_kernel()
{
    int idx = blockIdx.x * blockDim.x + threadIdx.x;
    const int total = M_ROWS * N_HEADS * 32;
    if (idx >= total) return;

    int d  = idx & 31;
    int h  = (idx >> 5) & (N_HEADS - 1);
    int bt = idx >> 9;
    int t  = bt & (SEQ - 1);

    float2 cs = g_rope[t * 32 + d];
    float c = cs.x, s = cs.y;

    size_t base = (size_t)bt * D_MODEL + h * HEAD_DIM + d;
    float x1 = g_q[base], x2 = g_q[base + 32];
    g_q[base]      = x1 * c - x2 * s;
    g_q[base + 32] = x2 * c + x1 * s;
    x1 = g_k[base]; x2 = g_k[base + 32];
    g_k[base]      = x1 * c - x2 * s;
    g_k[base + 32] = x2 * c + x1 * s;
}

// ---------------------------------------------------------------------------
// Tensor-core causal flash attention (unchanged from round 4 — performed to
// prediction). Block: 64 query rows, 128 threads = 4 warps (16 rows each).
// ---------------------------------------------------------------------------
#define FR 66            // padded frag stride (64 + 2)
#define SM_KHI 0
#define SM_KLO (64 * FR)
#define SM_VHI (128 * FR)
#define SM_VLO (192 * FR)
#define SM_P   (256 * FR)
#define FLASH_SMEM_FLOATS (256 * FR + 4096)
#define FLASH_SMEM_BYTES  (FLASH_SMEM_FLOATS * 4)

__global__ __launch_bounds__(128) void flash_tc_kernel()
{
    extern __shared__ float sm[];

    const int tid  = threadIdx.x;
    const int lane = tid & 31;
    const int w    = tid >> 5;
    const int qt   = gridDim.x - 1 - blockIdx.x;   // big blocks first
    const int q0   = qt * 64;
    const int h    = blockIdx.y;
    const int b    = blockIdx.z;

    const int rquad = lane >> 2;
    const int lmod  = lane & 3;
    const int rowA  = q0 + w * 16 + rquad;
    const int rowB  = rowA + 8;

    const float* kbase = g_k + (size_t)(b * SEQ) * D_MODEL + h * HEAD_DIM;
    const float* vbase = g_v + (size_t)(b * SEQ) * D_MODEL + h * HEAD_DIM;

    uint32_t qhi[8][4], qlo[8][4];
    {
        const float* qr0 = g_q + (size_t)(b * SEQ + rowA) * D_MODEL + h * HEAD_DIM;
        const float* qr1 = qr0 + 8 * D_MODEL;
#pragma unroll
        for (int kf = 0; kf < 8; kf++) {
            float a0 = qr0[kf * 8 + lmod]     * 0.125f;
            float a1 = qr1[kf * 8 + lmod]     * 0.125f;
            float a2 = qr0[kf * 8 + lmod + 4] * 0.125f;
            float a3 = qr1[kf * 8 + lmod + 4] * 0.125f;
            split_tf32(a0, qhi[kf][0], qlo[kf][0]);
            split_tf32(a1, qhi[kf][1], qlo[kf][1]);
            split_tf32(a2, qhi[kf][2], qlo[kf][2]);
            split_tf32(a3, qhi[kf][3], qlo[kf][3]);
        }
    }

    float oacc[8][4] = {};
    float mA = -1e30f, mB = -1e30f;
    float lA = 0.0f,   lB = 0.0f;

    const int ntiles = qt + 1;

    for (int kt = 0; kt < ntiles; kt++) {
        const int kstart = kt * 64;
        const bool diag = (kt == ntiles - 1);

#pragma unroll
        for (int pass = 0; pass < 8; pass++) {
            int t  = tid + pass * 128;
            int n  = t >> 4;
            int q4 = t & 15;
            size_t goff = (size_t)(kstart + n) * D_MODEL + q4 * 4;
            float4 kv = *(const float4*)(kbase + goff);
            float4 vv = *(const float4*)(vbase + goff);
            int kf   = q4 >> 1;
            int slot = q4 & 1;
            int kaddr = ((n >> 3) * 8 + kf) * FR + ((n & 7) << 3) + slot;
            float kv4[4] = {kv.x, kv.y, kv.z, kv.w};
            float vv4[4] = {vv.x, vv.y, vv.z, vv.w};
#pragma unroll
            for (int j = 0; j < 4; j++) {
                uint32_t hh, ll;
                split_tf32(kv4[j], hh, ll);
                sm[SM_KHI + kaddr + j * 2] = __uint_as_float(hh);
                sm[SM_KLO + kaddr + j * 2] = __uint_as_float(ll);
            }
            int vf    = (n >> 3) * 8 + (q4 >> 1);
            int vslot = (n >> 2) & 1;
            int dlo   = (q4 & 1) * 4;
#pragma unroll
            for (int j = 0; j < 4; j++) {
                uint32_t hh, ll;
                split_tf32(vv4[j], hh, ll);
                int vaddr = vf * FR + ((dlo + j) * 4 + (n & 3)) * 2 + vslot;
                sm[SM_VHI + vaddr] = __uint_as_float(hh);
                sm[SM_VLO + vaddr] = __uint_as_float(ll);
            }
        }
        __syncthreads();

        float c[8][4] = {};
#pragma unroll
        for (int kf = 0; kf < 8; kf++) {
#pragma unroll
            for (int nf = 0; nf < 8; nf++) {
                int a = (nf * 8 + kf) * FR + lane * 2;
                float2 h2 = *(const float2*)&sm[SM_KHI + a];
                float2 l2 = *(const float2*)&sm[SM_KLO + a];
                uint32_t bh[2] = {__float_as_uint(h2.x), __float_as_uint(h2.y)};
                uint32_t bl[2] = {__float_as_uint(l2.x), __float_as_uint(l2.y)};
                mma_tf32(c[nf], qhi[kf], bh);
                mma_tf32(c[nf], qhi[kf], bl);
                mma_tf32(c[nf], qlo[kf], bh);
            }
        }

        if (diag) {
#pragma unroll
            for (int nf = 0; nf < 8; nf++) {
                int col = kstart + nf * 8 + 2 * lmod;
                if (col     > rowA) c[nf][0] = -1e30f;
                if (col + 1 > rowA) c[nf][1] = -1e30f;
                if (col     > rowB) c[nf][2] = -1e30f;
                if (col + 1 > rowB) c[nf][3] = -1e30f;
            }
        }

        float tmA = -1e30f, tmB = -1e30f;
#pragma unroll
        for (int nf = 0; nf < 8; nf++) {
            tmA = fmaxf(tmA, fmaxf(c[nf][0], c[nf][1]));
            tmB = fmaxf(tmB, fmaxf(c[nf][2], c[nf][3]));
        }
        tmA = fmaxf(tmA, __shfl_xor_sync(0xffffffffu, tmA, 1));
        tmA = fmaxf(tmA, __shfl_xor_sync(0xffffffffu, tmA, 2));
        tmB = fmaxf(tmB, __shfl_xor_sync(0xffffffffu, tmB, 1));
        tmB = fmaxf(tmB, __shfl_xor_sync(0xffffffffu, tmB, 2));

        float nmA = fmaxf(mA, tmA), nmB = fmaxf(mB, tmB);
        float fA = __expf(mA - nmA), fB = __expf(mB - nmB);
        mA = nmA; mB = nmB;
        lA *= fA; lB *= fB;
#pragma unroll
        for (int nf = 0; nf < 8; nf++) {
            oacc[nf][0] *= fA; oacc[nf][1] *= fA;
            oacc[nf][2] *= fB; oacc[nf][3] *= fB;
        }

#pragma unroll
        for (int nf = 0; nf < 8; nf++) {
            float p0 = __expf(c[nf][0] - mA);
            float p1 = __expf(c[nf][1] - mA);
            float p2 = __expf(c[nf][2] - mB);
            float p3 = __expf(c[nf][3] - mB);
            lA += p0 + p1;
            lB += p2 + p3;
            *(float4*)&sm[SM_P + ((w * 8 + nf) * 32 + lane) * 4] =
                make_float4(p0, p1, p2, p3);
        }
        __syncwarp();

        const int pA0base = (lane >> 2) * 4 + ((lane & 3) >> 1);
        const int pbit    = lane & 1;
#pragma unroll
        for (int kf = 0; kf < 8; kf++) {
            int fb = (w * 8 + kf) * 32;
            float p0 = sm[SM_P + (fb + pA0base) * 4 + pbit];
            float p1 = sm[SM_P + (fb + pA0base) * 4 + pbit + 2];
            float p2 = sm[SM_P + (fb + pA0base + 2) * 4 + pbit];
            float p3 = sm[SM_P + (fb + pA0base + 2) * 4 + pbit + 2];
            uint32_t phi[4], plo[4];
            split_tf32(p0, phi[0], plo[0]);
            split_tf32(p1, phi[1], plo[1]);
            split_tf32(p2, phi[2], plo[2]);
            split_tf32(p3, phi[3], plo[3]);
#pragma unroll
            for (int nf = 0; nf < 8; nf++) {
                int a = (kf * 8 + nf) * FR + lane * 2;
                float2 h2 = *(const float2*)&sm[SM_VHI + a];
                float2 l2 = *(const float2*)&sm[SM_VLO + a];
                uint32_t bh[2] = {__float_as_uint(h2.x), __float_as_uint(h2.y)};
                uint32_t bl[2] = {__float_as_uint(l2.x), __float_as_uint(l2.y)};
                mma_tf32(oacc[nf], phi, bh);
                mma_tf32(oacc[nf], phi, bl);
                mma_tf32(oacc[nf], plo, bh);
            }
        }
        __syncthreads();
    }

    lA += __shfl_xor_sync(0xffffffffu, lA, 1);
    lA += __shfl_xor_sync(0xffffffffu, lA, 2);
    lB += __shfl_xor_sync(0xffffffffu, lB, 1);
    lB += __shfl_xor_sync(0xffffffffu, lB, 2);
    float iA = 1.0f / lA, iB = 1.0f / lB;

    float* outA = g_att + (size_t)(b * SEQ + rowA) * D_MODEL + h * HEAD_DIM;
    float* outB = g_att + (size_t)(b * SEQ + rowB) * D_MODEL + h * HEAD_DIM;
#pragma unroll
    for (int nf = 0; nf < 8; nf++) {
        int col = nf * 8 + 2 * lmod;
        *(float2*)(outA + col) = make_float2(oacc[nf][0] * iA, oacc[nf][1] * iA);
        *(float2*)(outB + col) = make_float2(oacc[nf][2] * iB, oacc[nf][3] * iB);
    }
}

// ---------------------------------------------------------------------------
extern "C" void kernel_launch(void* const* d_in, const int* in_sizes, int n_in,
                              void* d_out, int out_size)
{
    const float* x  = (const float*)d_in[0];
    const float* Wq = (const float*)d_in[1];
    const float* Wk = (const float*)d_in[2];
    const float* Wv = (const float*)d_in[3];
    const float* Wo = (const float*)d_in[4];
    float* out = (float*)d_out;

    float *q, *k, *v, *att;
    cudaGetSymbolAddress((void**)&q,   g_q);
    cudaGetSymbolAddress((void**)&k,   g_k);
    cudaGetSymbolAddress((void**)&v,   g_v);
    cudaGetSymbolAddress((void**)&att, g_att);

    cudaFuncSetAttribute(flash_tc_kernel,
                         cudaFuncAttributeMaxDynamicSharedMemorySize,
                         FLASH_SMEM_BYTES);

    dim3 ggrid(D_MODEL / BN, M_ROWS / BM);   // (8, 64)

    rope_table_kernel<<<(SEQ * 32 + 255) / 256, 256>>>();

    gemm_tf32_kernel<<<ggrid, 256>>>(x, Wq, q, M_ROWS, D_MODEL, D_MODEL);
    gemm_tf32_kernel<<<ggrid, 256>>>(x, Wk, k, M_ROWS, D_MODEL, D_MODEL);
    gemm_tf32_kernel<<<ggrid, 256>>>(x, Wv, v, M_ROWS, D_MODEL, D_MODEL);

    const int rope_total = M_ROWS * N_HEADS * 32;
    rope_apply_kernel<<<(rope_total + 255) / 256, 256>>>();

    flash_tc_kernel<<<dim3(SEQ / 64, N_HEADS, BATCH), 128, FLASH_SMEM_BYTES>>>();

    gemm_tf32_kernel<<<ggrid, 256>>>(att, Wo, out, M_ROWS, D_MODEL, D_MODEL);
}